// round 10
// baseline (speedup 1.0000x reference)
#include <cuda_runtime.h>
#include <cstdint>

#define B_    64
#define T_    2048
#define DIN   256
#define DH    256
#define DC    256
#define DOUT  256
#define G3    768   // 3 gates * 256

// Scratch (allocation-free rule: __device__ globals)
__device__ float g_Gx[(size_t)B_ * T_ * G3];  // x-part gate preactivations (+bias)
__device__ float g_H [(size_t)B_ * T_ * DH];  // h_t for all t (for output GEMM)

// ---------------- helpers ----------------

__device__ __forceinline__ float2 ffma2(float2 a, float2 b, float2 c) {
    union U { float2 f; unsigned long long u; };
    U ua, ub, uc, ud;
    ua.f = a; ub.f = b; uc.f = c;
    asm("fma.rn.f32x2 %0, %1, %2, %3;"
        : "=l"(ud.u) : "l"(ua.u), "l"(ub.u), "l"(uc.u));
    return ud.f;
}

__device__ __forceinline__ uint32_t smem_u32(const void* p) {
    uint32_t a;
    asm("{ .reg .u64 t; cvta.to.shared.u64 t, %1; cvt.u32.u64 %0, t; }"
        : "=r"(a) : "l"(p));
    return a;
}

__device__ __forceinline__ void cluster_sync_() {
    asm volatile("barrier.cluster.arrive.aligned;" ::: "memory");
    asm volatile("barrier.cluster.wait.aligned;" ::: "memory");
}

__device__ __forceinline__ void mbar_init1(uint32_t mbar) {
    asm volatile("mbarrier.init.shared.b64 [%0], %1;" :: "r"(mbar), "r"(1u) : "memory");
}

__device__ __forceinline__ void mbar_expect(uint32_t mbar, uint32_t bytes) {
    asm volatile("mbarrier.arrive.expect_tx.shared.b64 _, [%0], %1;"
                 :: "r"(mbar), "r"(bytes) : "memory");
}

__device__ __forceinline__ void mbar_wait(uint32_t mbar, uint32_t parity) {
    asm volatile(
        "{\n\t"
        ".reg .pred P;\n"
        "W%=:\n\t"
        "mbarrier.try_wait.parity.acquire.cta.shared::cta.b64 P, [%0], %1, 0x989680;\n\t"
        "@P bra.uni D%=;\n\t"
        "bra.uni W%=;\n"
        "D%=:\n\t"
        "}"
        :: "r"(mbar), "r"(parity) : "memory");
}

// store one f32 into rank's smem + count 4 tx bytes on that rank's mbarrier
__device__ __forceinline__ void st_async_remote(uint32_t laddr, uint32_t lmbar,
                                                uint32_t rank, float v) {
    asm volatile(
        "{\n\t"
        ".reg .b32 ra, rb;\n\t"
        "mapa.shared::cluster.u32 ra, %0, %2;\n\t"
        "mapa.shared::cluster.u32 rb, %1, %2;\n\t"
        "st.async.shared::cluster.mbarrier::complete_tx::bytes.b32 [ra], %3, [rb];\n\t"
        "}"
        :: "r"(laddr), "r"(lmbar), "r"(rank), "r"(__float_as_uint(v)) : "memory");
}

__device__ __forceinline__ float sigmoidf_(float x) {
    return __fdividef(1.0f, 1.0f + __expf(-x));
}

__device__ __forceinline__ float tanhf_(float x) {
    return 1.0f - __fdividef(2.0f, 1.0f + __expf(2.0f * x));
}

// ================= GEMM core: 128x128 tile, BK=16, double-buffered, 512 threads ======
// Micro-tile 8x4 f32x2. Per warp ty is CONSTANT -> A smem reads are uniform-address
// broadcasts; B reads 2 LDS.128 per kp. 16 warps/SM for latency hiding.

__global__ __launch_bounds__(512) void gemm_gx(
    const float* __restrict__ X,
    const float* __restrict__ Wf, const float* __restrict__ Wi, const float* __restrict__ Wo,
    const float* __restrict__ bf, const float* __restrict__ bi, const float* __restrict__ bo,
    const int* __restrict__ Np)
{
    const int N = *Np;
    const int m0 = blockIdx.y * 128;
    if (m0 >= B_ * N) return;
    const int j0v = blockIdx.x * 128;
    const int g  = j0v >> 8;
    const int d0 = j0v & 255;
    const float* Wg = (g == 0) ? Wf : ((g == 1) ? Wi : Wo);
    const float* bg = (g == 0) ? bf : ((g == 1) ? bi : bo);

    __shared__ float2 As2[2][8][128];
    __shared__ float2 Bs2[2][8][128];

    const int tid = threadIdx.x;
    const int tx = tid & 31, ty = tid >> 5;   // ty constant per warp

    // A loader: row = tid/4, k-offset = (tid&3)*4 (one float4/thread/chunk)
    const int ra = tid >> 2;
    const int ka = (tid & 3) << 2;
    int mg = m0 + ra; if (mg >= B_ * N) mg = B_ * N - 1;
    const int bb = mg / N, tt = mg % N;
    const float* arow = X + (size_t)(bb * T_ + tt) * DIN + ka;

    // B loader: k-row kb = tid/32, 4 consecutive cols nb
    const int kb = tid >> 5;
    const int nb = (tid & 31) << 2;
    const float* brow = Wg + (size_t)kb * DC + d0 + nb;
    float* bsf = reinterpret_cast<float*>(Bs2);
    const int bso = ((kb >> 1) * 128 + nb) * 2 + (kb & 1);   // within one buffer
    const int bufstride = 8 * 128 * 2;

    float4 av, bv;

    av = *reinterpret_cast<const float4*>(arow);
    bv = *reinterpret_cast<const float4*>(brow);
    As2[0][(ka >> 1) + 0][ra] = make_float2(av.x, av.y);
    As2[0][(ka >> 1) + 1][ra] = make_float2(av.z, av.w);
    bsf[bso + 0] = bv.x; bsf[bso + 2] = bv.y; bsf[bso + 4] = bv.z; bsf[bso + 6] = bv.w;
    __syncthreads();

    float2 acc[8][4];
    #pragma unroll
    for (int i = 0; i < 8; i++)
        #pragma unroll
        for (int j = 0; j < 4; j++) acc[i][j] = make_float2(0.f, 0.f);

    #pragma unroll 1
    for (int c = 0; c < 16; ++c) {
        const int buf = c & 1;
        if (c + 1 < 16) {
            const int kk = (c + 1) * 16;
            av = *reinterpret_cast<const float4*>(arow + kk);
            bv = *reinterpret_cast<const float4*>(brow + (size_t)kk * DC);
        }
        #pragma unroll
        for (int kp = 0; kp < 8; kp++) {
            float2 a2[8], b2[4];
            #pragma unroll
            for (int i = 0; i < 4; i++) {
                float4 t = *reinterpret_cast<const float4*>(&As2[buf][kp][32 * i + 2 * ty]);
                a2[2 * i]     = make_float2(t.x, t.y);
                a2[2 * i + 1] = make_float2(t.z, t.w);
            }
            {
                float4 t0 = *reinterpret_cast<const float4*>(&Bs2[buf][kp][2 * tx]);
                float4 t1 = *reinterpret_cast<const float4*>(&Bs2[buf][kp][64 + 2 * tx]);
                b2[0] = make_float2(t0.x, t0.y); b2[1] = make_float2(t0.z, t0.w);
                b2[2] = make_float2(t1.x, t1.y); b2[3] = make_float2(t1.z, t1.w);
            }
            #pragma unroll
            for (int i = 0; i < 8; i++)
                #pragma unroll
                for (int j = 0; j < 4; j++)
                    acc[i][j] = ffma2(a2[i], b2[j], acc[i][j]);
        }
        if (c + 1 < 16) {
            const int nbuf = buf ^ 1;
            As2[nbuf][(ka >> 1) + 0][ra] = make_float2(av.x, av.y);
            As2[nbuf][(ka >> 1) + 1][ra] = make_float2(av.z, av.w);
            float* bp = bsf + nbuf * bufstride + bso;
            bp[0] = bv.x; bp[2] = bv.y; bp[4] = bv.z; bp[6] = bv.w;
        }
        __syncthreads();
    }

    const float bg0 = bg[d0 + 2 * tx],      bg1 = bg[d0 + 2 * tx + 1];
    const float bg2 = bg[d0 + 64 + 2 * tx], bg3 = bg[d0 + 64 + 2 * tx + 1];
    #pragma unroll
    for (int i = 0; i < 8; i++) {
        const int m = m0 + 32 * (i >> 1) + 2 * ty + (i & 1);
        if (m < B_ * N) {
            float* crow = g_Gx + (size_t)m * G3 + j0v;
            *reinterpret_cast<float2*>(crow + 2 * tx) =
                make_float2(acc[i][0].x + acc[i][0].y + bg0,
                            acc[i][1].x + acc[i][1].y + bg1);
            *reinterpret_cast<float2*>(crow + 64 + 2 * tx) =
                make_float2(acc[i][2].x + acc[i][2].y + bg2,
                            acc[i][3].x + acc[i][3].y + bg3);
        }
    }
}

// ---------------- GEMM 3: outs = sigmoid(H @ Wout + bout) ----------------

__global__ __launch_bounds__(512) void gemm_out(
    const float* __restrict__ Wout, const float* __restrict__ bout,
    float* __restrict__ out, const int* __restrict__ Np)
{
    const int N = *Np;
    const int m0 = blockIdx.y * 128;
    if (m0 >= B_ * N) return;
    const int j0v = blockIdx.x * 128;

    __shared__ float2 As2[2][8][128];
    __shared__ float2 Bs2[2][8][128];

    const int tid = threadIdx.x;
    const int tx = tid & 31, ty = tid >> 5;

    const int ra = tid >> 2;
    const int ka = (tid & 3) << 2;
    int mg = m0 + ra; if (mg >= B_ * N) mg = B_ * N - 1;
    const float* arow = g_H + (size_t)mg * DH + ka;

    const int kb = tid >> 5;
    const int nb = (tid & 31) << 2;
    const float* brow = Wout + (size_t)kb * DOUT + j0v + nb;
    float* bsf = reinterpret_cast<float*>(Bs2);
    const int bso = ((kb >> 1) * 128 + nb) * 2 + (kb & 1);
    const int bufstride = 8 * 128 * 2;

    float4 av, bv;

    av = *reinterpret_cast<const float4*>(arow);
    bv = *reinterpret_cast<const float4*>(brow);
    As2[0][(ka >> 1) + 0][ra] = make_float2(av.x, av.y);
    As2[0][(ka >> 1) + 1][ra] = make_float2(av.z, av.w);
    bsf[bso + 0] = bv.x; bsf[bso + 2] = bv.y; bsf[bso + 4] = bv.z; bsf[bso + 6] = bv.w;
    __syncthreads();

    float2 acc[8][4];
    #pragma unroll
    for (int i = 0; i < 8; i++)
        #pragma unroll
        for (int j = 0; j < 4; j++) acc[i][j] = make_float2(0.f, 0.f);

    #pragma unroll 1
    for (int c = 0; c < 16; ++c) {
        const int buf = c & 1;
        if (c + 1 < 16) {
            const int kk = (c + 1) * 16;
            av = *reinterpret_cast<const float4*>(arow + kk);
            bv = *reinterpret_cast<const float4*>(brow + (size_t)kk * DOUT);
        }
        #pragma unroll
        for (int kp = 0; kp < 8; kp++) {
            float2 a2[8], b2[4];
            #pragma unroll
            for (int i = 0; i < 4; i++) {
                float4 t = *reinterpret_cast<const float4*>(&As2[buf][kp][32 * i + 2 * ty]);
                a2[2 * i]     = make_float2(t.x, t.y);
                a2[2 * i + 1] = make_float2(t.z, t.w);
            }
            {
                float4 t0 = *reinterpret_cast<const float4*>(&Bs2[buf][kp][2 * tx]);
                float4 t1 = *reinterpret_cast<const float4*>(&Bs2[buf][kp][64 + 2 * tx]);
                b2[0] = make_float2(t0.x, t0.y); b2[1] = make_float2(t0.z, t0.w);
                b2[2] = make_float2(t1.x, t1.y); b2[3] = make_float2(t1.z, t1.w);
            }
            #pragma unroll
            for (int i = 0; i < 8; i++)
                #pragma unroll
                for (int j = 0; j < 4; j++)
                    acc[i][j] = ffma2(a2[i], b2[j], acc[i][j]);
        }
        if (c + 1 < 16) {
            const int nbuf = buf ^ 1;
            As2[nbuf][(ka >> 1) + 0][ra] = make_float2(av.x, av.y);
            As2[nbuf][(ka >> 1) + 1][ra] = make_float2(av.z, av.w);
            float* bp = bsf + nbuf * bufstride + bso;
            bp[0] = bv.x; bp[2] = bv.y; bp[4] = bv.z; bp[6] = bv.w;
        }
        __syncthreads();
    }

    const float b0v = bout[j0v + 2 * tx],      b1v = bout[j0v + 2 * tx + 1];
    const float b2v = bout[j0v + 64 + 2 * tx], b3v = bout[j0v + 64 + 2 * tx + 1];
    #pragma unroll
    for (int i = 0; i < 8; i++) {
        const int m = m0 + 32 * (i >> 1) + 2 * ty + (i & 1);
        if (m < B_ * N) {
            float* crow = out + (size_t)m * DOUT + j0v;
            *reinterpret_cast<float2*>(crow + 2 * tx) =
                make_float2(sigmoidf_(acc[i][0].x + acc[i][0].y + b0v),
                            sigmoidf_(acc[i][1].x + acc[i][1].y + b1v));
            *reinterpret_cast<float2*>(crow + 64 + 2 * tx) =
                make_float2(sigmoidf_(acc[i][2].x + acc[i][2].y + b2v),
                            sigmoidf_(acc[i][3].x + acc[i][3].y + b3v));
        }
    }
}

// ---------------- Recurrence: persistent, batch-parallel, 4-CTA clusters ----------------
// As R9 (quarter-split GEMV, st.async transport) PLUS: gate activations are applied by
// the 384 writer lanes (sigmoid for f/o cols; sigmoid+tanh for i cols — gate is
// warp-uniform, no divergence). Owner phase is just c = c*f + z*i; h = tanh(c)*o,
// leaving ONE serial MUFU chain in the 128-thread tail.

__global__ __launch_bounds__(384, 1) __cluster_dims__(4, 1, 1)
void lstm_rec(
    const float* __restrict__ h0, const float* __restrict__ c0,
    const float* __restrict__ Wf, const float* __restrict__ Wi, const float* __restrict__ Wo,
    float* __restrict__ out, const int* __restrict__ Np)
{
    const int N   = *Np;
    const int r   = blockIdx.x & 3;
    const int cid = blockIdx.x >> 2;
    const int b0  = cid * 2;
    const int tid = threadIdx.x;

    __shared__ __align__(16) float h_s[2][2][256];   // [parity][batch][dim]
    __shared__ float pre_s[2][208];                  // activated gate values
    __shared__ float zi_s[2][72];                    // tanh(pre_i) (z)
    __shared__ __align__(8) unsigned long long mbar[2];

    const int lane = tid & 31;
    const int wrp  = tid >> 5;
    const int kq   = lane & 3;                        // k-interleave slot
    const int cc0  = wrp * 16 + ((lane >> 2) << 1);   // first of 2 local gate-cols
    const int g0   = cc0 >> 6;                        // gate (warp-uniform)
    const int gd0  = r * 64 + (cc0 & 63);
    const float* Wg = (g0 == 0) ? Wf : ((g0 == 1) ? Wi : Wo);

    // weights: w0/w1 = cols cc0/cc0+1; per line li: k0 = 4*kq + 16*li (h-part rows +256)
    float2 w0[32], w1[32];
    #pragma unroll
    for (int li = 0; li < 16; li++) {
        const int k0 = 4 * kq + 16 * li;
        const float* p0 = Wg + (size_t)(256 + k0) * DC + gd0;
        w0[2 * li]     = make_float2(p0[0],          p0[DC]);
        w0[2 * li + 1] = make_float2(p0[2 * DC],     p0[3 * DC]);
        w1[2 * li]     = make_float2(p0[1],          p0[DC + 1]);
        w1[2 * li + 1] = make_float2(p0[2 * DC + 1], p0[3 * DC + 1]);
    }

    // writer identity after reduction: lane kq ends with target (bw, cw)
    const int bw = kq >> 1;
    const int cw = cc0 + (kq & 1);
    const int gcolw = (cw >> 6) * 256 + r * 64 + (cw & 63);   // col in Gx layout [f|i|o]
    const bool is_igate = (g0 == 1);

    const uint32_t mb0 = smem_u32(&mbar[0]);
    const uint32_t mb1 = smem_u32(&mbar[1]);
    if (tid == 0) {
        mbar_init1(mb0);
        mbar_init1(mb1);
        mbar_expect(mb0, 2048);   // first use: h for step 2
        mbar_expect(mb1, 2048);   // first use: h for step 1
    }

    // init h (parity 0)
    for (int i = tid; i < 512; i += 384) {
        const int b = i >> 8, d = i & 255;
        h_s[0][b][d] = h0[(b0 + b) * DH + d];
    }
    float c_st = 0.f, h_loc = 0.f;
    const int pb = (tid < 128) ? (tid >> 6) : 0;
    const int pd = (tid < 128) ? (tid & 63) : 0;
    if (tid < 128) c_st = c0[(b0 + pb) * DC + r * 64 + pd];
    __syncthreads();
    cluster_sync_();   // all mbarriers initialized before any DSMEM traffic

    float gx = g_Gx[((size_t)(b0 + bw) * N + 0) * G3 + gcolw];

    float* out_hf = out + (size_t)B_ * N * DOUT;
    float* out_cf = out_hf + B_ * DH;

    int ph0 = 0, ph1 = 0;

    for (int t = 0; t < N; t++) {
        const int p = t & 1;

        if (t > 0) {
            const uint32_t mb = p ? mb1 : mb0;
            mbar_wait(mb, (uint32_t)(p ? ph1 : ph0));
            if (p) ph1 ^= 1; else ph0 ^= 1;
            if (tid == 0) mbar_expect(mb, 2048);   // re-arm for step t+2
        }

        const float gxc = gx;
        const int tn = (t + 1 < N) ? (t + 1) : t;
        gx = g_Gx[((size_t)(b0 + bw) * N + tn) * G3 + gcolw];

        // GEMV: acc[col][batch], h lines at byte offset kq*16 + li*64
        float2 a00 = make_float2(0.f, 0.f), a10 = a00, a01 = a00, a11 = a00;
        {
            const float4* hp0 = reinterpret_cast<const float4*>(&h_s[p][0][4 * kq]);
            const float4* hp1 = reinterpret_cast<const float4*>(&h_s[p][1][4 * kq]);
            #pragma unroll
            for (int li = 0; li < 16; li++) {
                float4 hv = hp0[4 * li];
                float2 hlo = make_float2(hv.x, hv.y), hhi = make_float2(hv.z, hv.w);
                a00 = ffma2(hlo, w0[2 * li], a00);
                a00 = ffma2(hhi, w0[2 * li + 1], a00);
                a10 = ffma2(hlo, w1[2 * li], a10);
                a10 = ffma2(hhi, w1[2 * li + 1], a10);
            }
            #pragma unroll
            for (int li = 0; li < 16; li++) {
                float4 hv = hp1[4 * li];
                float2 hlo = make_float2(hv.x, hv.y), hhi = make_float2(hv.z, hv.w);
                a01 = ffma2(hlo, w0[2 * li], a01);
                a01 = ffma2(hhi, w0[2 * li + 1], a01);
                a11 = ffma2(hlo, w1[2 * li], a11);
                a11 = ffma2(hhi, w1[2 * li + 1], a11);
            }
        }
        // targets: 0=(b0,c0) 1=(b0,c1) 2=(b1,c0) 3=(b1,c1)
        const float v0 = a00.x + a00.y;
        const float v1 = a10.x + a10.y;
        const float v2 = a01.x + a01.y;
        const float v3 = a11.x + a11.y;

        const bool bit0 = (kq & 1), bit1 = (kq & 2);
        // round 1 (xor 1): combine kq-pairs; packed send/keep
        float sendA = bit0 ? v0 : v1, keepA = bit0 ? v1 : v0;
        float tA = keepA + __shfl_xor_sync(0xffffffffu, sendA, 1);
        float sendB = bit0 ? v2 : v3, keepB = bit0 ? v3 : v2;
        float tB = keepB + __shfl_xor_sync(0xffffffffu, sendB, 1);
        // round 2 (xor 2): combine kq-half-pairs
        float send2 = bit1 ? tA : tB, keep2 = bit1 ? tB : tA;
        float sfin = keep2 + __shfl_xor_sync(0xffffffffu, send2, 2);

        // apply activation at the writer (gate is warp-uniform)
        const float pre = sfin + gxc;
        pre_s[bw][cw] = sigmoidf_(pre);
        if (is_igate) zi_s[bw][cw - 64] = tanhf_(pre);
        __syncthreads();

        if (tid < 128) {
            const float f  = pre_s[pb][pd];
            const float ig = pre_s[pb][64 + pd];
            const float z  = zi_s[pb][pd];
            const float o  = pre_s[pb][128 + pd];
            c_st  = c_st * f + z * ig;
            h_loc = tanhf_(c_st) * o;

            if (t + 1 < N) {
                // push h chunk to all 4 ranks' h_s[1-p] + count tx on their mbar
                const uint32_t la = smem_u32(&h_s[1 - p][pb][r * 64 + pd]);
                const uint32_t lb = p ? mb0 : mb1;
                st_async_remote(la, lb, 0u, h_loc);
                st_async_remote(la, lb, 1u, h_loc);
                st_async_remote(la, lb, 2u, h_loc);
                st_async_remote(la, lb, 3u, h_loc);
            }
            g_H[((size_t)(b0 + pb) * N + t) * DH + r * 64 + pd] = h_loc;
        }
    }

    if (tid < 128) {
        out_hf[(b0 + pb) * DH + r * 64 + pd] = h_loc;
        out_cf[(b0 + pb) * DC + r * 64 + pd] = c_st;
    }
    cluster_sync_();   // no CTA exits while peers could still be mid-step
}

// ---------------- launch ----------------

extern "C" void kernel_launch(void* const* d_in, const int* in_sizes, int n_in,
                              void* d_out, int out_size) {
    const float* x    = (const float*)d_in[0];
    const float* h0   = (const float*)d_in[1];
    const float* c0   = (const float*)d_in[2];
    const float* Wf   = (const float*)d_in[3];
    const float* bfp  = (const float*)d_in[4];
    const float* Wi   = (const float*)d_in[5];
    const float* bip  = (const float*)d_in[6];
    const float* Wo   = (const float*)d_in[7];
    const float* bop  = (const float*)d_in[8];
    const float* Wout = (const float*)d_in[9];
    const float* bout = (const float*)d_in[10];
    const int*   Np   = (const int*)d_in[11];
    float* out = (float*)d_out;

    dim3 g1(G3 / 128, B_ * T_ / 128);
    gemm_gx<<<g1, 512>>>(x, Wf, Wi, Wo, bfp, bip, bop, Np);

    lstm_rec<<<128, 384>>>(h0, c0, Wf, Wi, Wo, out, Np);

    dim3 g3(DOUT / 128, B_ * T_ / 128);
    gemm_out<<<g3, 512>>>(Wout, bout, out, Np);
}